// round 17
// baseline (speedup 1.0000x reference)
#include <cuda_runtime.h>
#include <math.h>

// Problem constants
#define S        2048
#define ROWS     65536            // 2*16*2048 rows of x; also 32*2048 gemm outputs
#define TNB      64               // t-tile per partial-GEMM block
#define KCB      64               // k-chunk per partial-GEMM block
#define KSPLIT   32               // 2048 / KCB
#define NTILES   (S / TNB)        // 32 t-tiles
#define SMPAD    68               // smem row stride (words): 16B-aligned, 68%32=4 -> conflict-free
#define AGRID    1184             // 148 SMs x 8 blocks: fully-resident persistent grid

// Scratch (allocation-free rule: __device__ globals)
__device__ int   g_idx[ROWS];
__device__ float g_gather[ROWS];
__device__ float g_part[KSPLIT * ROWS];   // 8 MB fp32 partials [ks][m][t]

// ---------------------------------------------------------------------------
// Kernel A: PERSISTENT warp-per-row. 1184 blocks x 8 warps, grid-stride over
// rows (~7 rows/warp). No barriers anywhere; 8-deep batched streaming loads
// (__ldcs) + streaming stores (__stcs); loads flow continuously across rows
// (no wave transitions, no block ramp/drain gaps).
// ---------------------------------------------------------------------------
__global__ void __launch_bounds__(256)
copy_argmax_kernel(const float* __restrict__ x, float* __restrict__ out)
{
    const int warp = threadIdx.x >> 5;
    const int lane = threadIdx.x & 31;
    const int vw   = blockIdx.x * 8 + warp;     // virtual warp id

    for (int row = vw; row < ROWS; row += AGRID * 8) {
        const float4* __restrict__ xr = (const float4*)(x + (size_t)row * S);
        float4* __restrict__ orow     = (float4*)(out + (size_t)row * S);

        float best = -INFINITY;
        int   bidx = 0;

        // 512 float4 per row, 16 per lane, in 2 batches of 8 (MLP=8).
        #pragma unroll
        for (int b = 0; b < 2; b++) {
            float4 v[8];
            #pragma unroll
            for (int i = 0; i < 8; i++)
                v[i] = __ldcs(xr + lane + (b * 8 + i) * 32);
            #pragma unroll
            for (int i = 0; i < 8; i++)
                __stcs(orow + lane + (b * 8 + i) * 32, v[i]);
            #pragma unroll
            for (int i = 0; i < 8; i++) {
                const int base = (lane + (b * 8 + i) * 32) * 4;
                if (v[i].x > best) { best = v[i].x; bidx = base + 0; }
                if (v[i].y > best) { best = v[i].y; bidx = base + 1; }
                if (v[i].z > best) { best = v[i].z; bidx = base + 2; }
                if (v[i].w > best) { best = v[i].w; bidx = base + 3; }
            }
        }

        // Warp reduction, first-occurrence tie-break (smaller index wins ties)
        #pragma unroll
        for (int off = 16; off > 0; off >>= 1) {
            float ov = __shfl_down_sync(0xFFFFFFFFu, best, off);
            int   oi = __shfl_down_sync(0xFFFFFFFFu, bidx, off);
            if (ov > best || (ov == best && oi < bidx)) { best = ov; bidx = oi; }
        }

        if (lane == 0) {
            g_idx[row]    = bidx;
            g_gather[row] = best;
        }
    }
}

// ---------------------------------------------------------------------------
// Async-copy + mma helpers
// ---------------------------------------------------------------------------
__device__ __forceinline__ void cp_async16(void* smem_dst, const void* gmem_src) {
    unsigned saddr = (unsigned)__cvta_generic_to_shared(smem_dst);
    asm volatile("cp.async.cg.shared.global [%0], [%1], 16;\n"
                 :: "r"(saddr), "l"(gmem_src));
}
__device__ __forceinline__ void cp_async_commit() {
    asm volatile("cp.async.commit_group;\n" ::: "memory");
}
__device__ __forceinline__ void cp_async_wait_all() {
    asm volatile("cp.async.wait_all;\n" ::: "memory");
}

__device__ __forceinline__ void mma_tf32_16x8x8(
    float& c0, float& c1, float& c2, float& c3,
    unsigned a0, unsigned a1, unsigned a2, unsigned a3,
    unsigned b0, unsigned b1)
{
    asm volatile(
        "mma.sync.aligned.m16n8k8.row.col.f32.tf32.tf32.f32 "
        "{%0,%1,%2,%3}, {%4,%5,%6,%7}, {%8,%9}, {%0,%1,%2,%3};"
        : "+f"(c0), "+f"(c1), "+f"(c2), "+f"(c3)
        : "r"(a0), "r"(a1), "r"(a2), "r"(a3), "r"(b0), "r"(b1));
}

// ---------------------------------------------------------------------------
// Kernel B1: k-split partial GEMM on tensor cores (tf32 mma.sync).
// Grid (32, 32) = 1024 blocks, 128 threads (4 warps). Unchanged from R13.
// ---------------------------------------------------------------------------
__global__ void __launch_bounds__(128)
gemm_partial_kernel(const float* __restrict__ W)
{
    __shared__ __align__(16) unsigned gs[32 * SMPAD];   // [m][k] fp32 bits
    __shared__ __align__(16) unsigned ws[TNB * SMPAD];  // [t][k] fp32 bits

    const int t0  = blockIdx.x * TNB;
    const int k0  = blockIdx.y * KCB;
    const int tid = threadIdx.x;

    // --- A-independent: W tile cp.async (overlaps the grid-dependency wait) ---
    {
        const int t  = tid >> 1;            // 0..63
        const int cb = (tid & 1) * 32;      // 0 or 32
        const float* src = W + (size_t)(t0 + t) * S + k0 + cb;
        unsigned*    dst = ws + t * SMPAD + cb;
        #pragma unroll
        for (int j = 0; j < 8; j++)
            cp_async16(dst + j * 4, src + j * 4);
    }
    cp_async_commit();

    cudaGridDependencySynchronize();

    // --- gather tile cp.async ---
    {
        const int m  = tid >> 2;            // 0..31
        const int cb = (tid & 3) * 16;      // 0,16,32,48
        const float* src = g_gather + (size_t)m * S + k0 + cb;
        unsigned*    dst = gs + m * SMPAD + cb;
        #pragma unroll
        for (int j = 0; j < 4; j++)
            cp_async16(dst + j * 4, src + j * 4);
    }
    cp_async_commit();
    cp_async_wait_all();
    __syncthreads();

    const int lane = tid & 31;
    const int w    = tid >> 5;
    const int mh   = (w & 1) * 16;     // m-half base
    const int tq   = (w >> 1) * 32;    // t-quarter base

    const int ar = lane >> 2;          // 0..7
    const int ac = lane & 3;           // 0..3

    float c[4][4] = {};

    #pragma unroll
    for (int ks = 0; ks < 8; ks++) {
        const int col = ks * 8 + ac;
        const unsigned a0 = gs[(mh + ar    ) * SMPAD + col];
        const unsigned a1 = gs[(mh + ar + 8) * SMPAD + col];
        const unsigned a2 = gs[(mh + ar    ) * SMPAD + col + 4];
        const unsigned a3 = gs[(mh + ar + 8) * SMPAD + col + 4];
        #pragma unroll
        for (int nt = 0; nt < 4; nt++) {
            const int n = tq + nt * 8 + ar;          // B[k][n] = ws[n][k]
            const unsigned b0 = ws[n * SMPAD + col];
            const unsigned b1 = ws[n * SMPAD + col + 4];
            mma_tf32_16x8x8(c[nt][0], c[nt][1], c[nt][2], c[nt][3],
                            a0, a1, a2, a3, b0, b1);
        }
    }

    // Store partials. C frag m16n8: (c0,c1) at row mh+ar, cols 2*ac, 2*ac+1;
    // (c2,c3) at row mh+ar+8.
    float* p = g_part + (size_t)blockIdx.y * ROWS;
    #pragma unroll
    for (int nt = 0; nt < 4; nt++) {
        const int tcol = t0 + tq + nt * 8 + 2 * ac;
        *(float2*)(p + (size_t)(mh + ar    ) * S + tcol) = make_float2(c[nt][0], c[nt][1]);
        *(float2*)(p + (size_t)(mh + ar + 8) * S + tcol) = make_float2(c[nt][2], c[nt][3]);
    }
}

// ---------------------------------------------------------------------------
// Kernel B2: reduce KSPLIT partials (fixed ks order -> deterministic), + bias,
// exact-erf GELU, scatter into out. 256 blocks x 128 threads, 2 outputs each
// via float2 over the L2-resident partials. PDL. Unchanged from R13.
// ---------------------------------------------------------------------------
__global__ void __launch_bounds__(128)
reduce_gelu_scatter_kernel(const float* __restrict__ bias,
                           float* __restrict__ out)
{
    const int r2 = (blockIdx.x * 128 + threadIdx.x) * 2;   // base of 2 outputs
    const int t  = r2 & (S - 1);
    const float bv0 = bias[t];
    const float bv1 = bias[t + 1];       // r2 even, t+1 < S (S even)

    cudaGridDependencySynchronize();

    float2 s = make_float2(0.f, 0.f);
    #pragma unroll
    for (int ks = 0; ks < KSPLIT; ks++) {
        float2 v = *(const float2*)(g_part + (size_t)ks * ROWS + r2);
        s.x += v.x; s.y += v.y;
    }

    const float v0  = s.x + bv0;
    const float v1  = s.y + bv1;
    const float g0 = 0.5f * v0 * (1.0f + erff(v0 * 0.70710678118654752f));
    const float g1 = 0.5f * v1 * (1.0f + erff(v1 * 0.70710678118654752f));
    out[(size_t)(r2    ) * S + (size_t)g_idx[r2    ]] = g0;
    out[(size_t)(r2 + 1) * S + (size_t)g_idx[r2 + 1]] = g1;
}

// ---------------------------------------------------------------------------
extern "C" void kernel_launch(void* const* d_in, const int* in_sizes, int n_in,
                              void* d_out, int out_size)
{
    const float* x    = (const float*)d_in[0];   // [2,16,2048,2048]
    const float* W    = (const float*)d_in[1];   // [2048,2048]
    const float* bias = (const float*)d_in[2];   // [2048]
    float* out        = (float*)d_out;

    copy_argmax_kernel<<<AGRID, 256>>>(x, out);

    {
        cudaLaunchConfig_t cfg = {};
        cfg.gridDim  = dim3(NTILES, KSPLIT);
        cfg.blockDim = dim3(128);
        cfg.stream   = 0;
        cudaLaunchAttribute attr[1];
        attr[0].id = cudaLaunchAttributeProgrammaticStreamSerialization;
        attr[0].val.programmaticStreamSerializationAllowed = 1;
        cfg.attrs = attr;
        cfg.numAttrs = 1;
        cudaLaunchKernelEx(&cfg, gemm_partial_kernel, W);
    }

    {
        cudaLaunchConfig_t cfg = {};
        cfg.gridDim  = dim3(ROWS / 256);
        cfg.blockDim = dim3(128);
        cfg.stream   = 0;
        cudaLaunchAttribute attr[1];
        attr[0].id = cudaLaunchAttributeProgrammaticStreamSerialization;
        attr[0].val.programmaticStreamSerializationAllowed = 1;
        cfg.attrs = attr;
        cfg.numAttrs = 1;
        cudaLaunchKernelEx(&cfg, reduce_gelu_scatter_kernel, bias, out);
    }
}